// round 9
// baseline (speedup 1.0000x reference)
#include <cuda_runtime.h>
#include <cuda_fp16.h>
#include <stdint.h>

#define M_DIM 4096
#define N_DIM 4096
#define K_DIM 1024
#define KC    512     // reference panel size (Eigen gebp kc)

__device__ float g_x[(size_t)M_DIM * K_DIM];
__device__ float g_w[(size_t)N_DIM * K_DIM];

// ---------------------------------------------------------------------------
// Decode: [n,16] pulse floats -> fp16 value -> fp32 (exact)
// ---------------------------------------------------------------------------
__global__ void decode_kernel(const float* __restrict__ pulse,
                              float* __restrict__ out, int n) {
    int i = blockIdx.x * blockDim.x + threadIdx.x;
    if (i >= n) return;
    const float4* p4 = reinterpret_cast<const float4*>(pulse + (size_t)i * 16);
    float4 a = p4[0], b = p4[1], c = p4[2], d = p4[3];
    float p[16] = {a.x, a.y, a.z, a.w, b.x, b.y, b.z, b.w,
                   c.x, c.y, c.z, c.w, d.x, d.y, d.z, d.w};
    unsigned int bits = 0;
#pragma unroll
    for (int j = 0; j < 16; j++)
        bits |= ((unsigned int)(p[j] > 0.5f)) << (15 - j);
    out[i] = __half2float(__ushort_as_half((unsigned short)bits));
}

// ---------------------------------------------------------------------------
// Half-K GEMM phase. Each output accumulated as a strict k-ascending
// sequential fp32 FMA chain over [koff, koff+KC). PHASE2 combines with the
// stashed partial (single RN add) and writes the pulse encoding.
// BM=BN=128, BK=16, 256 threads, 8x8 microtile.
// ---------------------------------------------------------------------------
#define BM 128
#define BN 128
#define BK 16

template <bool PHASE2>
__global__ __launch_bounds__(256, 2)
void gemm_phase_kernel(const float* __restrict__ A,
                       const float* __restrict__ Bm,
                       float* __restrict__ out, int koff) {
    __shared__ float As[BK][BM];
    __shared__ float Bs[BK][BN];

    const int tid = threadIdx.x;
    const int tx = tid & 15;
    const int ty = tid >> 4;
    const int m0 = blockIdx.y * BM;
    const int n0 = blockIdx.x * BN;

    const int lr = tid >> 2;        // row 0..63
    const int lc = (tid & 3) * 4;   // k col 0,4,8,12

    float acc[8][8];
#pragma unroll
    for (int i = 0; i < 8; i++)
#pragma unroll
        for (int j = 0; j < 8; j++) acc[i][j] = 0.0f;

    for (int k0 = koff; k0 < koff + KC; k0 += BK) {
#pragma unroll
        for (int s = 0; s < 2; s++) {
            int row = lr + s * 64;
            float4 v = *reinterpret_cast<const float4*>(
                &A[(size_t)(m0 + row) * K_DIM + k0 + lc]);
            As[lc + 0][row] = v.x;
            As[lc + 1][row] = v.y;
            As[lc + 2][row] = v.z;
            As[lc + 3][row] = v.w;
        }
#pragma unroll
        for (int s = 0; s < 2; s++) {
            int row = lr + s * 64;
            float4 v = *reinterpret_cast<const float4*>(
                &Bm[(size_t)(n0 + row) * K_DIM + k0 + lc]);
            Bs[lc + 0][row] = v.x;
            Bs[lc + 1][row] = v.y;
            Bs[lc + 2][row] = v.z;
            Bs[lc + 3][row] = v.w;
        }
        __syncthreads();

#pragma unroll
        for (int k = 0; k < BK; k++) {
            float ar[8], br[8];
            float4 a0 = *reinterpret_cast<const float4*>(&As[k][ty * 8]);
            float4 a1 = *reinterpret_cast<const float4*>(&As[k][ty * 8 + 4]);
            float4 b0 = *reinterpret_cast<const float4*>(&Bs[k][tx * 8]);
            float4 b1 = *reinterpret_cast<const float4*>(&Bs[k][tx * 8 + 4]);
            ar[0] = a0.x; ar[1] = a0.y; ar[2] = a0.z; ar[3] = a0.w;
            ar[4] = a1.x; ar[5] = a1.y; ar[6] = a1.z; ar[7] = a1.w;
            br[0] = b0.x; br[1] = b0.y; br[2] = b0.z; br[3] = b0.w;
            br[4] = b1.x; br[5] = b1.y; br[6] = b1.z; br[7] = b1.w;
#pragma unroll
            for (int i = 0; i < 8; i++)
#pragma unroll
                for (int j = 0; j < 8; j++)
                    acc[i][j] = fmaf(ar[i], br[j], acc[i][j]);
        }
        __syncthreads();
    }

    if (!PHASE2) {
        // stash b0 (raw fp32) in slot 0 of each output's 16-float group
#pragma unroll
        for (int i = 0; i < 8; i++) {
            const int m = m0 + ty * 8 + i;
#pragma unroll
            for (int j = 0; j < 8; j++) {
                const int n = n0 + tx * 8 + j;
                out[((size_t)m * N_DIM + n) * 16] = acc[i][j];
            }
        }
    } else {
#pragma unroll
        for (int i = 0; i < 8; i++) {
            const int m = m0 + ty * 8 + i;
#pragma unroll
            for (int j = 0; j < 8; j++) {
                const int n = n0 + tx * 8 + j;
                float* base = out + ((size_t)m * N_DIM + n) * 16;
                float b0v = *base;                 // stashed partial
                float r = b0v + acc[i][j];         // single RN combine
                unsigned int u =
                    (unsigned int)__half_as_ushort(__float2half_rn(r));
                float4* dst = reinterpret_cast<float4*>(base);
                float4 o;
                o.x = (float)((u >> 15) & 1); o.y = (float)((u >> 14) & 1);
                o.z = (float)((u >> 13) & 1); o.w = (float)((u >> 12) & 1);
                dst[0] = o;
                o.x = (float)((u >> 11) & 1); o.y = (float)((u >> 10) & 1);
                o.z = (float)((u >>  9) & 1); o.w = (float)((u >>  8) & 1);
                dst[1] = o;
                o.x = (float)((u >>  7) & 1); o.y = (float)((u >>  6) & 1);
                o.z = (float)((u >>  5) & 1); o.w = (float)((u >>  4) & 1);
                dst[2] = o;
                o.x = (float)((u >>  3) & 1); o.y = (float)((u >>  2) & 1);
                o.z = (float)((u >>  1) & 1); o.w = (float)((u >>  0) & 1);
                dst[3] = o;
            }
        }
    }
}

// ---------------------------------------------------------------------------
extern "C" void kernel_launch(void* const* d_in, const int* in_sizes, int n_in,
                              void* d_out, int out_size) {
    const float* x_pulse = (const float*)d_in[0];
    const float* w_pulse = (const float*)d_in[1];
    float* out = (float*)d_out;

    float* gx = nullptr;
    float* gw = nullptr;
    cudaGetSymbolAddress((void**)&gx, g_x);
    cudaGetSymbolAddress((void**)&gw, g_w);

    const int n_x = M_DIM * K_DIM;
    const int n_w = N_DIM * K_DIM;

    decode_kernel<<<(n_x + 255) / 256, 256>>>(x_pulse, gx, n_x);
    decode_kernel<<<(n_w + 255) / 256, 256>>>(w_pulse, gw, n_w);

    dim3 grid(N_DIM / BN, M_DIM / BM);  // 32 x 32
    gemm_phase_kernel<false><<<grid, 256>>>(gx, gw, out, 0);
    gemm_phase_kernel<true><<<grid, 256>>>(gx, gw, out, KC);
}

// round 10
// speedup vs baseline: 1.3305x; 1.3305x over previous
#include <cuda_runtime.h>
#include <cuda_fp16.h>
#include <stdint.h>

#define M_DIM 4096
#define N_DIM 4096
#define K_DIM 1024
#define KC    512     // reference panel size (two sequential chains + RN add)

typedef unsigned long long ull;

__device__ float g_x[(size_t)M_DIM * K_DIM];   // decoded X
__device__ float g_w[(size_t)N_DIM * K_DIM];   // decoded W
__device__ float g_p[(size_t)M_DIM * N_DIM];   // phase-1 partials (coalesced)

// ---------------------------------------------------------------------------
// packed f32x2 helpers — per-lane IEEE RN fma (bit-identical to scalar fmaf)
// ---------------------------------------------------------------------------
__device__ __forceinline__ ull pack2(float x) {
    ull r;
    asm("mov.b64 %0, {%1, %1};" : "=l"(r) : "f"(x));
    return r;
}
__device__ __forceinline__ void fma2(ull& d, ull a, ull b) {
    asm("fma.rn.f32x2 %0, %1, %2, %0;" : "+l"(d) : "l"(a), "l"(b));
}
__device__ __forceinline__ float lo2(ull v) {
    return __uint_as_float((unsigned int)(v & 0xffffffffull));
}
__device__ __forceinline__ float hi2(ull v) {
    return __uint_as_float((unsigned int)(v >> 32));
}

// ---------------------------------------------------------------------------
// Decode: [n,16] pulse floats -> fp16 value -> fp32 (exact)
// ---------------------------------------------------------------------------
__global__ void decode_kernel(const float* __restrict__ pulse,
                              float* __restrict__ out, int n) {
    int i = blockIdx.x * blockDim.x + threadIdx.x;
    if (i >= n) return;
    const float4* p4 = reinterpret_cast<const float4*>(pulse + (size_t)i * 16);
    float4 a = p4[0], b = p4[1], c = p4[2], d = p4[3];
    float p[16] = {a.x, a.y, a.z, a.w, b.x, b.y, b.z, b.w,
                   c.x, c.y, c.z, c.w, d.x, d.y, d.z, d.w};
    unsigned int bits = 0;
#pragma unroll
    for (int j = 0; j < 16; j++)
        bits |= ((unsigned int)(p[j] > 0.5f)) << (15 - j);
    out[i] = __half2float(__ushort_as_half((unsigned short)bits));
}

// ---------------------------------------------------------------------------
// Half-K GEMM phase with FFMA2 math + register prefetch pipelining.
// Per output: strict k-ascending fp32 RN chain over [koff, koff+KC).
// Phase1 stashes partials to g_p (coalesced); Phase2 combines (single RN
// add), rounds to fp16, writes pulse encoding.
// BM=BN=128, BK=16, 256 threads, 8x8 microtile (acc held as 8x4 f32x2).
// ---------------------------------------------------------------------------
#define BM 128
#define BN 128
#define BK 16

template <bool PHASE2>
__global__ __launch_bounds__(256, 2)
void gemm_phase_kernel(const float* __restrict__ A,
                       const float* __restrict__ Bm,
                       float* __restrict__ part,
                       float* __restrict__ out, int koff) {
    __shared__ float As[BK][BM];
    __shared__ float Bs[BK][BN];

    const int tid = threadIdx.x;
    const int tx = tid & 15;        // n micro 0..15
    const int ty = tid >> 4;        // m micro 0..15
    const int m0 = blockIdx.y * BM;
    const int n0 = blockIdx.x * BN;

    const int lr = tid >> 2;        // load row 0..63
    const int lc = (tid & 3) * 4;   // load k col 0,4,8,12

    ull acc2[8][4];
#pragma unroll
    for (int i = 0; i < 8; i++)
#pragma unroll
        for (int j = 0; j < 4; j++) acc2[i][j] = 0ull;

    const float* aptr0 = &A[(size_t)(m0 + lr) * K_DIM + koff + lc];
    const float* aptr1 = aptr0 + (size_t)64 * K_DIM;
    const float* bptr0 = &Bm[(size_t)(n0 + lr) * K_DIM + koff + lc];
    const float* bptr1 = bptr0 + (size_t)64 * K_DIM;

    // prologue: fetch tile 0
    float4 ra0 = *reinterpret_cast<const float4*>(aptr0);
    float4 ra1 = *reinterpret_cast<const float4*>(aptr1);
    float4 rb0 = *reinterpret_cast<const float4*>(bptr0);
    float4 rb1 = *reinterpret_cast<const float4*>(bptr1);

    const int NT = KC / BK;  // 32 tiles
    for (int t = 0; t < NT; t++) {
        // store staged tile to smem
        As[lc + 0][lr] = ra0.x; As[lc + 1][lr] = ra0.y;
        As[lc + 2][lr] = ra0.z; As[lc + 3][lr] = ra0.w;
        As[lc + 0][lr + 64] = ra1.x; As[lc + 1][lr + 64] = ra1.y;
        As[lc + 2][lr + 64] = ra1.z; As[lc + 3][lr + 64] = ra1.w;
        Bs[lc + 0][lr] = rb0.x; Bs[lc + 1][lr] = rb0.y;
        Bs[lc + 2][lr] = rb0.z; Bs[lc + 3][lr] = rb0.w;
        Bs[lc + 0][lr + 64] = rb1.x; Bs[lc + 1][lr + 64] = rb1.y;
        Bs[lc + 2][lr + 64] = rb1.z; Bs[lc + 3][lr + 64] = rb1.w;
        __syncthreads();

        // prefetch next tile while computing this one
        if (t + 1 < NT) {
            const int o = (t + 1) * BK;
            ra0 = *reinterpret_cast<const float4*>(aptr0 + o);
            ra1 = *reinterpret_cast<const float4*>(aptr1 + o);
            rb0 = *reinterpret_cast<const float4*>(bptr0 + o);
            rb1 = *reinterpret_cast<const float4*>(bptr1 + o);
        }

#pragma unroll
        for (int k = 0; k < BK; k++) {
            float4 a0 = *reinterpret_cast<const float4*>(&As[k][ty * 8]);
            float4 a1 = *reinterpret_cast<const float4*>(&As[k][ty * 8 + 4]);
            ull ar2[8];
            ar2[0] = pack2(a0.x); ar2[1] = pack2(a0.y);
            ar2[2] = pack2(a0.z); ar2[3] = pack2(a0.w);
            ar2[4] = pack2(a1.x); ar2[5] = pack2(a1.y);
            ar2[6] = pack2(a1.z); ar2[7] = pack2(a1.w);
            const ull* bp = reinterpret_cast<const ull*>(&Bs[k][tx * 8]);
            ull br2[4] = {bp[0], bp[1], bp[2], bp[3]};
#pragma unroll
            for (int i = 0; i < 8; i++)
#pragma unroll
                for (int j = 0; j < 4; j++)
                    fma2(acc2[i][j], ar2[i], br2[j]);
        }
        __syncthreads();
    }

    if (!PHASE2) {
        // coalesced stash of fp32 partials
#pragma unroll
        for (int i = 0; i < 8; i++) {
            const int m = m0 + ty * 8 + i;
            float* dst = part + (size_t)m * N_DIM + n0 + tx * 8;
            float4 v0 = make_float4(lo2(acc2[i][0]), hi2(acc2[i][0]),
                                    lo2(acc2[i][1]), hi2(acc2[i][1]));
            float4 v1 = make_float4(lo2(acc2[i][2]), hi2(acc2[i][2]),
                                    lo2(acc2[i][3]), hi2(acc2[i][3]));
            reinterpret_cast<float4*>(dst)[0] = v0;
            reinterpret_cast<float4*>(dst)[1] = v1;
        }
    } else {
#pragma unroll
        for (int i = 0; i < 8; i++) {
            const int m = m0 + ty * 8 + i;
            const float* psrc = part + (size_t)m * N_DIM + n0 + tx * 8;
            float4 p0 = reinterpret_cast<const float4*>(psrc)[0];
            float4 p1 = reinterpret_cast<const float4*>(psrc)[1];
            float pv[8] = {p0.x, p0.y, p0.z, p0.w, p1.x, p1.y, p1.z, p1.w};
            float bv[8] = {lo2(acc2[i][0]), hi2(acc2[i][0]),
                           lo2(acc2[i][1]), hi2(acc2[i][1]),
                           lo2(acc2[i][2]), hi2(acc2[i][2]),
                           lo2(acc2[i][3]), hi2(acc2[i][3])};
#pragma unroll
            for (int j = 0; j < 8; j++) {
                const int n = n0 + tx * 8 + j;
                float r = pv[j] + bv[j];   // single RN combine of panels
                unsigned int u =
                    (unsigned int)__half_as_ushort(__float2half_rn(r));
                float4* dst = reinterpret_cast<float4*>(
                    out + ((size_t)m * N_DIM + n) * 16);
                float4 o;
                o.x = (float)((u >> 15) & 1); o.y = (float)((u >> 14) & 1);
                o.z = (float)((u >> 13) & 1); o.w = (float)((u >> 12) & 1);
                dst[0] = o;
                o.x = (float)((u >> 11) & 1); o.y = (float)((u >> 10) & 1);
                o.z = (float)((u >>  9) & 1); o.w = (float)((u >>  8) & 1);
                dst[1] = o;
                o.x = (float)((u >>  7) & 1); o.y = (float)((u >>  6) & 1);
                o.z = (float)((u >>  5) & 1); o.w = (float)((u >>  4) & 1);
                dst[2] = o;
                o.x = (float)((u >>  3) & 1); o.y = (float)((u >>  2) & 1);
                o.z = (float)((u >>  1) & 1); o.w = (float)((u >>  0) & 1);
                dst[3] = o;
            }
        }
    }
}

// ---------------------------------------------------------------------------
extern "C" void kernel_launch(void* const* d_in, const int* in_sizes, int n_in,
                              void* d_out, int out_size) {
    const float* x_pulse = (const float*)d_in[0];
    const float* w_pulse = (const float*)d_in[1];
    float* out = (float*)d_out;

    float *gx = nullptr, *gw = nullptr, *gp = nullptr;
    cudaGetSymbolAddress((void**)&gx, g_x);
    cudaGetSymbolAddress((void**)&gw, g_w);
    cudaGetSymbolAddress((void**)&gp, g_p);

    const int n_x = M_DIM * K_DIM;
    const int n_w = N_DIM * K_DIM;

    decode_kernel<<<(n_x + 255) / 256, 256>>>(x_pulse, gx, n_x);
    decode_kernel<<<(n_w + 255) / 256, 256>>>(w_pulse, gw, n_w);

    dim3 grid(N_DIM / BN, M_DIM / BM);  // 32 x 32
    gemm_phase_kernel<false><<<grid, 256>>>(gx, gw, gp, out, 0);
    gemm_phase_kernel<true><<<grid, 256>>>(gx, gw, gp, out, KC);
}

// round 11
// speedup vs baseline: 1.4969x; 1.1250x over previous
#include <cuda_runtime.h>
#include <cuda_fp16.h>
#include <stdint.h>

#define M_DIM 4096
#define N_DIM 4096
#define K_DIM 1024
#define KC    512     // reference panel size (two sequential chains + RN add)

typedef unsigned long long ull;

__device__ float g_x[(size_t)M_DIM * K_DIM];   // decoded X
__device__ float g_w[(size_t)N_DIM * K_DIM];   // decoded W
__device__ float g_p[(size_t)M_DIM * N_DIM];   // phase-1 partials

// ---------------------------------------------------------------------------
// packed f32x2 helpers — per-lane IEEE RN fma (bit-identical to scalar fmaf)
// ---------------------------------------------------------------------------
__device__ __forceinline__ ull pack2(float x) {
    ull r;
    asm("mov.b64 %0, {%1, %1};" : "=l"(r) : "f"(x));
    return r;
}
__device__ __forceinline__ void fma2(ull& d, ull a, ull b) {
    asm("fma.rn.f32x2 %0, %1, %2, %0;" : "+l"(d) : "l"(a), "l"(b));
}
__device__ __forceinline__ float lo2(ull v) {
    return __uint_as_float((unsigned int)(v & 0xffffffffull));
}
__device__ __forceinline__ float hi2(ull v) {
    return __uint_as_float((unsigned int)(v >> 32));
}

// ---------------------------------------------------------------------------
// Decode: [n,16] pulse floats -> fp16 value -> fp32 (exact)
// ---------------------------------------------------------------------------
__global__ void decode_kernel(const float* __restrict__ pulse,
                              float* __restrict__ out, int n) {
    int i = blockIdx.x * blockDim.x + threadIdx.x;
    if (i >= n) return;
    const float4* p4 = reinterpret_cast<const float4*>(pulse + (size_t)i * 16);
    float4 a = p4[0], b = p4[1], c = p4[2], d = p4[3];
    float p[16] = {a.x, a.y, a.z, a.w, b.x, b.y, b.z, b.w,
                   c.x, c.y, c.z, c.w, d.x, d.y, d.z, d.w};
    unsigned int bits = 0;
#pragma unroll
    for (int j = 0; j < 16; j++)
        bits |= ((unsigned int)(p[j] > 0.5f)) << (15 - j);
    out[i] = __half2float(__ushort_as_half((unsigned short)bits));
}

// ---------------------------------------------------------------------------
// Half-K GEMM phase, FFMA2 math, conflict-free smem fragment loads.
// Thread (tx,ty): m in {m0+ty*8+0..7}, n in {n0 + tx*2+e + 32j}, e=0..1,
// j=0..3. acc2[i][j] = f32x2 pair over (n, n+1).
// Per output: strict k-ascending fp32 RN chain over [koff, koff+KC).
// ---------------------------------------------------------------------------
#define BM 128
#define BN 128
#define BK 16

template <bool PHASE2>
__global__ __launch_bounds__(256, 2)
void gemm_phase_kernel(const float* __restrict__ A,
                       const float* __restrict__ Bm,
                       float* __restrict__ part,
                       float* __restrict__ out, int koff) {
    __shared__ float As[BK][BM];
    __shared__ float Bs[BK][BN];

    const int tid = threadIdx.x;
    const int tx = tid & 15;        // n micro 0..15
    const int ty = tid >> 4;        // m micro 0..15
    const int m0 = blockIdx.y * BM;
    const int n0 = blockIdx.x * BN;

    const int lr = tid >> 2;        // load row 0..63
    const int lc = (tid & 3) * 4;   // load k col 0,4,8,12

    ull acc2[8][4];
#pragma unroll
    for (int i = 0; i < 8; i++)
#pragma unroll
        for (int j = 0; j < 4; j++) acc2[i][j] = 0ull;

    const float* aptr0 = &A[(size_t)(m0 + lr) * K_DIM + koff + lc];
    const float* aptr1 = aptr0 + (size_t)64 * K_DIM;
    const float* bptr0 = &Bm[(size_t)(n0 + lr) * K_DIM + koff + lc];
    const float* bptr1 = bptr0 + (size_t)64 * K_DIM;

    float4 ra0 = *reinterpret_cast<const float4*>(aptr0);
    float4 ra1 = *reinterpret_cast<const float4*>(aptr1);
    float4 rb0 = *reinterpret_cast<const float4*>(bptr0);
    float4 rb1 = *reinterpret_cast<const float4*>(bptr1);

    const int NT = KC / BK;  // 32 tiles
    for (int t = 0; t < NT; t++) {
        As[lc + 0][lr] = ra0.x; As[lc + 1][lr] = ra0.y;
        As[lc + 2][lr] = ra0.z; As[lc + 3][lr] = ra0.w;
        As[lc + 0][lr + 64] = ra1.x; As[lc + 1][lr + 64] = ra1.y;
        As[lc + 2][lr + 64] = ra1.z; As[lc + 3][lr + 64] = ra1.w;
        Bs[lc + 0][lr] = rb0.x; Bs[lc + 1][lr] = rb0.y;
        Bs[lc + 2][lr] = rb0.z; Bs[lc + 3][lr] = rb0.w;
        Bs[lc + 0][lr + 64] = rb1.x; Bs[lc + 1][lr + 64] = rb1.y;
        Bs[lc + 2][lr + 64] = rb1.z; Bs[lc + 3][lr + 64] = rb1.w;
        __syncthreads();

        if (t + 1 < NT) {
            const int o = (t + 1) * BK;
            ra0 = *reinterpret_cast<const float4*>(aptr0 + o);
            ra1 = *reinterpret_cast<const float4*>(aptr1 + o);
            rb0 = *reinterpret_cast<const float4*>(bptr0 + o);
            rb1 = *reinterpret_cast<const float4*>(bptr1 + o);
        }

#pragma unroll
        for (int k = 0; k < BK; k++) {
            float4 a0 = *reinterpret_cast<const float4*>(&As[k][ty * 8]);
            float4 a1 = *reinterpret_cast<const float4*>(&As[k][ty * 8 + 4]);
            ull ar2[8];
            ar2[0] = pack2(a0.x); ar2[1] = pack2(a0.y);
            ar2[2] = pack2(a0.z); ar2[3] = pack2(a0.w);
            ar2[4] = pack2(a1.x); ar2[5] = pack2(a1.y);
            ar2[6] = pack2(a1.z); ar2[7] = pack2(a1.w);
            // conflict-free: 16 lanes at 8B stride cover all 32 banks
            ull br2[4];
#pragma unroll
            for (int j = 0; j < 4; j++)
                br2[j] = *reinterpret_cast<const ull*>(&Bs[k][tx * 2 + 32 * j]);
#pragma unroll
            for (int i = 0; i < 8; i++)
#pragma unroll
                for (int j = 0; j < 4; j++)
                    fma2(acc2[i][j], ar2[i], br2[j]);
        }
        __syncthreads();
    }

    if (!PHASE2) {
#pragma unroll
        for (int i = 0; i < 8; i++) {
            const int m = m0 + ty * 8 + i;
            float* dst = part + (size_t)m * N_DIM + n0 + tx * 2;
#pragma unroll
            for (int j = 0; j < 4; j++) {
                float2 v = make_float2(lo2(acc2[i][j]), hi2(acc2[i][j]));
                *reinterpret_cast<float2*>(dst + 32 * j) = v;
            }
        }
    } else {
#pragma unroll
        for (int i = 0; i < 8; i++) {
            const int m = m0 + ty * 8 + i;
            const float* psrc = part + (size_t)m * N_DIM + n0 + tx * 2;
#pragma unroll
            for (int j = 0; j < 4; j++) {
                float2 pv = *reinterpret_cast<const float2*>(psrc + 32 * j);
                float rv[2] = {pv.x + lo2(acc2[i][j]),
                               pv.y + hi2(acc2[i][j])};
#pragma unroll
                for (int e = 0; e < 2; e++) {
                    const int n = n0 + tx * 2 + e + 32 * j;
                    unsigned int u = (unsigned int)
                        __half_as_ushort(__float2half_rn(rv[e]));
                    float4* dst = reinterpret_cast<float4*>(
                        out + ((size_t)m * N_DIM + n) * 16);
#pragma unroll
                    for (int q = 0; q < 4; q++) {
                        float4 o;
                        o.x = __uint_as_float(
                            (unsigned)(((int)(u << (16 + q * 4 + 0))) >> 31)
                            & 0x3F800000u);
                        o.y = __uint_as_float(
                            (unsigned)(((int)(u << (16 + q * 4 + 1))) >> 31)
                            & 0x3F800000u);
                        o.z = __uint_as_float(
                            (unsigned)(((int)(u << (16 + q * 4 + 2))) >> 31)
                            & 0x3F800000u);
                        o.w = __uint_as_float(
                            (unsigned)(((int)(u << (16 + q * 4 + 3))) >> 31)
                            & 0x3F800000u);
                        dst[q] = o;
                    }
                }
            }
        }
    }
}

// ---------------------------------------------------------------------------
extern "C" void kernel_launch(void* const* d_in, const int* in_sizes, int n_in,
                              void* d_out, int out_size) {
    const float* x_pulse = (const float*)d_in[0];
    const float* w_pulse = (const float*)d_in[1];
    float* out = (float*)d_out;

    float *gx = nullptr, *gw = nullptr, *gp = nullptr;
    cudaGetSymbolAddress((void**)&gx, g_x);
    cudaGetSymbolAddress((void**)&gw, g_w);
    cudaGetSymbolAddress((void**)&gp, g_p);

    const int n_x = M_DIM * K_DIM;
    const int n_w = N_DIM * K_DIM;

    decode_kernel<<<(n_x + 255) / 256, 256>>>(x_pulse, gx, n_x);
    decode_kernel<<<(n_w + 255) / 256, 256>>>(w_pulse, gw, n_w);

    dim3 grid(N_DIM / BN, M_DIM / BM);  // 32 x 32
    gemm_phase_kernel<false><<<grid, 256>>>(gx, gw, gp, out, 0);
    gemm_phase_kernel<true><<<grid, 256>>>(gx, gw, gp, out, KC);
}

// round 13
// speedup vs baseline: 1.6615x; 1.1100x over previous
#include <cuda_runtime.h>
#include <cuda_fp16.h>
#include <stdint.h>

#define M_DIM 4096
#define N_DIM 4096
#define K_DIM 1024
#define KC    512     // reference panel size (two sequential chains + RN add)

typedef unsigned long long ull;

__device__ float g_xT[(size_t)K_DIM * M_DIM];  // decoded X, k-major [K][M]
__device__ float g_wT[(size_t)K_DIM * N_DIM];  // decoded W, k-major [K][N]
__device__ float g_p[(size_t)M_DIM * N_DIM];   // phase-1 partials

// ---------------------------------------------------------------------------
// helpers
// ---------------------------------------------------------------------------
__device__ __forceinline__ uint32_t smem_u32(const void* p) {
    uint32_t a;
    asm("{ .reg .u64 t; cvta.to.shared.u64 t, %1; cvt.u32.u64 %0, t; }"
        : "=r"(a) : "l"(p));
    return a;
}
#define CP16(saddr, gptr) \
    asm volatile("cp.async.cg.shared.global [%0], [%1], 16;" \
                 :: "r"(saddr), "l"(gptr) : "memory")
#define CP_COMMIT() asm volatile("cp.async.commit_group;" ::: "memory")
#define CP_WAIT1()  asm volatile("cp.async.wait_group 1;" ::: "memory")

__device__ __forceinline__ ull pack2(float x) {
    ull r;
    asm("mov.b64 %0, {%1, %1};" : "=l"(r) : "f"(x));
    return r;
}
__device__ __forceinline__ void fma2(ull& d, ull a, ull b) {
    asm("fma.rn.f32x2 %0, %1, %2, %0;" : "+l"(d) : "l"(a), "l"(b));
}
__device__ __forceinline__ float lo2(ull v) {
    return __uint_as_float((unsigned int)(v & 0xffffffffull));
}
__device__ __forceinline__ float hi2(ull v) {
    return __uint_as_float((unsigned int)(v >> 32));
}

// ---------------------------------------------------------------------------
// Decode + transpose: pulse[(m*K+k)*16] -> outT[k*4096 + m]  (exact values)
// ---------------------------------------------------------------------------
__global__ void decode_transpose_kernel(const float* __restrict__ pulse,
                                        float* __restrict__ outT) {
    int i = blockIdx.x * blockDim.x + threadIdx.x;   // i = k*4096 + m
    int m = i & 4095;
    int k = i >> 12;
    const float4* p4 =
        reinterpret_cast<const float4*>(pulse + ((size_t)m * K_DIM + k) * 16);
    float4 a = p4[0], b = p4[1], c = p4[2], d = p4[3];
    float p[16] = {a.x, a.y, a.z, a.w, b.x, b.y, b.z, b.w,
                   c.x, c.y, c.z, c.w, d.x, d.y, d.z, d.w};
    unsigned int bits = 0;
#pragma unroll
    for (int j = 0; j < 16; j++)
        bits |= ((unsigned int)(p[j] > 0.5f)) << (15 - j);
    outT[i] = __half2float(__ushort_as_half((unsigned short)bits));
}

// ---------------------------------------------------------------------------
// Half-K GEMM phase: cp.async 3-stage pipeline + fragment double buffering.
// Per output: strict k-ascending fp32 RN chain over [koff, koff+KC)
// (FFMA2 = per-lane IEEE RN, pairs over adjacent n; chain order unchanged).
// BM=BN=128, TILE_K=16, 256 threads, 8x8 microtile.
// ---------------------------------------------------------------------------
#define TILE_K 16
#define NT (KC / TILE_K)                    // 32
#define STAGE_FLOATS (TILE_K * 128)         // 2048
#define NSTAGE 3
#define SMEM_BYTES (NSTAGE * STAGE_FLOATS * 2 * 4)  // 49152

template <bool PHASE2>
__global__ __launch_bounds__(256, 1)
void gemm_phase_kernel(const float* __restrict__ AT,   // [K][M]
                       const float* __restrict__ BT,   // [K][N]
                       float* __restrict__ part,
                       float* __restrict__ out, int koff) {
    extern __shared__ float sm[];
    float* Asm = sm;                               // [NSTAGE][16][128]
    float* Bsm = sm + NSTAGE * STAGE_FLOATS;

    const int tid = threadIdx.x;
    const int tx = tid & 15;
    const int ty = tid >> 4;
    const int m0 = blockIdx.y * 128;
    const int n0 = blockIdx.x * 128;

    // copy indexing: tile = 16 rows x 32 chunks(16B); 512 chunks; 2/thread/op
    const int r0 = tid >> 5;               // chunk set 0: row 0..7
    const int c0 = (tid & 31) * 4;
    const int r1 = (tid + 256) >> 5;        // chunk set 1: row 8..15
    const int c1 = c0;

    const uint32_t sA = smem_u32(Asm);
    const uint32_t sB = smem_u32(Bsm);

    ull acc2[8][4];
#pragma unroll
    for (int i = 0; i < 8; i++)
#pragma unroll
        for (int j = 0; j < 4; j++) acc2[i][j] = 0ull;

#define ISSUE(T)                                                              \
    do {                                                                      \
        const int _st = (T) % NSTAGE;                                         \
        const size_t _k0 = (size_t)(koff + (T) * TILE_K);                     \
        CP16(sA + (uint32_t)(_st * STAGE_FLOATS + r0 * 128 + c0) * 4,         \
             AT + (_k0 + r0) * M_DIM + m0 + c0);                              \
        CP16(sA + (uint32_t)(_st * STAGE_FLOATS + r1 * 128 + c1) * 4,         \
             AT + (_k0 + r1) * M_DIM + m0 + c1);                              \
        CP16(sB + (uint32_t)(_st * STAGE_FLOATS + r0 * 128 + c0) * 4,         \
             BT + (_k0 + r0) * N_DIM + n0 + c0);                              \
        CP16(sB + (uint32_t)(_st * STAGE_FLOATS + r1 * 128 + c1) * 4,         \
             BT + (_k0 + r1) * N_DIM + n0 + c1);                              \
        CP_COMMIT();                                                          \
    } while (0)

    ISSUE(0);
    ISSUE(1);

    for (int t = 0; t < NT; t++) {
        CP_WAIT1();          // this thread's tile-t copies landed
        __syncthreads();     // all threads' copies of tile t visible
        if (t + 2 < NT) ISSUE(t + 2);
        else CP_COMMIT();    // keep group counting uniform

        const int st = t % NSTAGE;
        const float* as = Asm + st * STAGE_FLOATS;
        const float* bs = Bsm + st * STAGE_FLOATS;

        // fragment double buffers
        float4 afA[2], afB[2];
        ull bfr[2][4];
        afA[0] = *reinterpret_cast<const float4*>(as + ty * 8);
        afB[0] = *reinterpret_cast<const float4*>(as + ty * 8 + 4);
#pragma unroll
        for (int j = 0; j < 4; j++)
            bfr[0][j] = *reinterpret_cast<const ull*>(bs + tx * 2 + 32 * j);

#pragma unroll
        for (int k = 0; k < TILE_K; k++) {
            const int cur = k & 1, nxt = cur ^ 1;
            if (k + 1 < TILE_K) {
                afA[nxt] = *reinterpret_cast<const float4*>(
                    as + (k + 1) * 128 + ty * 8);
                afB[nxt] = *reinterpret_cast<const float4*>(
                    as + (k + 1) * 128 + ty * 8 + 4);
#pragma unroll
                for (int j = 0; j < 4; j++)
                    bfr[nxt][j] = *reinterpret_cast<const ull*>(
                        bs + (k + 1) * 128 + tx * 2 + 32 * j);
            }
            ull ar2[8];
            ar2[0] = pack2(afA[cur].x); ar2[1] = pack2(afA[cur].y);
            ar2[2] = pack2(afA[cur].z); ar2[3] = pack2(afA[cur].w);
            ar2[4] = pack2(afB[cur].x); ar2[5] = pack2(afB[cur].y);
            ar2[6] = pack2(afB[cur].z); ar2[7] = pack2(afB[cur].w);
#pragma unroll
            for (int i = 0; i < 8; i++)
#pragma unroll
                for (int j = 0; j < 4; j++)
                    fma2(acc2[i][j], ar2[i], bfr[cur][j]);
        }
    }
#undef ISSUE

    if (!PHASE2) {
#pragma unroll
        for (int i = 0; i < 8; i++) {
            const int m = m0 + ty * 8 + i;
            float* dst = part + (size_t)m * N_DIM + n0 + tx * 2;
#pragma unroll
            for (int j = 0; j < 4; j++) {
                float2 v = make_float2(lo2(acc2[i][j]), hi2(acc2[i][j]));
                *reinterpret_cast<float2*>(dst + 32 * j) = v;
            }
        }
    } else {
#pragma unroll
        for (int i = 0; i < 8; i++) {
            const int m = m0 + ty * 8 + i;
            const float* psrc = part + (size_t)m * N_DIM + n0 + tx * 2;
#pragma unroll
            for (int j = 0; j < 4; j++) {
                float2 pv = *reinterpret_cast<const float2*>(psrc + 32 * j);
                float rv[2] = {pv.x + lo2(acc2[i][j]),
                               pv.y + hi2(acc2[i][j])};
#pragma unroll
                for (int e = 0; e < 2; e++) {
                    const int n = n0 + tx * 2 + e + 32 * j;
                    unsigned int u = (unsigned int)
                        __half_as_ushort(__float2half_rn(rv[e]));
                    float4* dst = reinterpret_cast<float4*>(
                        out + ((size_t)m * N_DIM + n) * 16);
#pragma unroll
                    for (int q = 0; q < 4; q++) {
                        float4 o;
                        o.x = __uint_as_float(
                            (unsigned)(((int)(u << (16 + q * 4 + 0))) >> 31)
                            & 0x3F800000u);
                        o.y = __uint_as_float(
                            (unsigned)(((int)(u << (16 + q * 4 + 1))) >> 31)
                            & 0x3F800000u);
                        o.z = __uint_as_float(
                            (unsigned)(((int)(u << (16 + q * 4 + 2))) >> 31)
                            & 0x3F800000u);
                        o.w = __uint_as_float(
                            (unsigned)(((int)(u << (16 + q * 4 + 3))) >> 31)
                            & 0x3F800000u);
                        dst[q] = o;
                    }
                }
            }
        }
    }
}

// ---------------------------------------------------------------------------
extern "C" void kernel_launch(void* const* d_in, const int* in_sizes, int n_in,
                              void* d_out, int out_size) {
    const float* x_pulse = (const float*)d_in[0];
    const float* w_pulse = (const float*)d_in[1];
    float* out = (float*)d_out;

    float *gx = nullptr, *gw = nullptr, *gp = nullptr;
    cudaGetSymbolAddress((void**)&gx, g_xT);
    cudaGetSymbolAddress((void**)&gw, g_wT);
    cudaGetSymbolAddress((void**)&gp, g_p);

    const int n_el = M_DIM * K_DIM;

    decode_transpose_kernel<<<n_el / 256, 256>>>(x_pulse, gx);
    decode_transpose_kernel<<<n_el / 256, 256>>>(w_pulse, gw);

    cudaFuncSetAttribute(gemm_phase_kernel<false>,
                         cudaFuncAttributeMaxDynamicSharedMemorySize,
                         SMEM_BYTES);
    cudaFuncSetAttribute(gemm_phase_kernel<true>,
                         cudaFuncAttributeMaxDynamicSharedMemorySize,
                         SMEM_BYTES);

    dim3 grid(N_DIM / 128, M_DIM / 128);  // 32 x 32
    gemm_phase_kernel<false><<<grid, 256, SMEM_BYTES>>>(gx, gw, gp, out, 0);
    gemm_phase_kernel<true><<<grid, 256, SMEM_BYTES>>>(gx, gw, gp, out, KC);
}